// round 1
// baseline (speedup 1.0000x reference)
#include <cuda_runtime.h>
#include <math.h>

#define S_TOK 8192
#define MDIM  1024
#define HDIM  4096
#define NEXP  8
#define CAP   1024   // S/E, capacity_factor 1.0, k=1

// ---------------- scratch (__device__ globals; no runtime alloc allowed) ----
__device__ int   g_eidx[S_TOK];
__device__ float g_gval[S_TOK];
__device__ int   g_slot_token[NEXP * CAP];
__device__ float g_slot_gate[NEXP * CAP];
__device__ float g_h[(size_t)NEXP * CAP * HDIM];   // 128 MB hidden activations

__device__ __forceinline__ float gelu_exact(float v) {
    // approximate=False gelu: x * 0.5 * (1 + erf(x/sqrt(2)))
    return 0.5f * v * (1.0f + erff(v * 0.70710678118654752440f));
}

// ---------------------------------------------------------------------------
// Gate: logits = x @ wg  [S,8]; softmax; argmax; gate value of the winner.
// One warp per token; wg (1024x8 = 32KB) staged in smem.
// ---------------------------------------------------------------------------
__global__ __launch_bounds__(256)
void gate_kernel(const float* __restrict__ x, const float* __restrict__ wg) {
    __shared__ float swg[MDIM * NEXP];
    for (int i = threadIdx.x; i < MDIM * NEXP; i += blockDim.x) swg[i] = wg[i];
    __syncthreads();

    int warp = threadIdx.x >> 5;
    int lane = threadIdx.x & 31;
    int s = blockIdx.x * 8 + warp;
    if (s >= S_TOK) return;

    const float* xr = x + (size_t)s * MDIM;
    float acc[NEXP];
#pragma unroll
    for (int e = 0; e < NEXP; e++) acc[e] = 0.f;

    for (int k = lane; k < MDIM; k += 32) {
        float xv = xr[k];
#pragma unroll
        for (int e = 0; e < NEXP; e++) acc[e] += xv * swg[k * NEXP + e];
    }
#pragma unroll
    for (int e = 0; e < NEXP; e++) {
#pragma unroll
        for (int o = 16; o > 0; o >>= 1) acc[e] += __shfl_xor_sync(0xFFFFFFFFu, acc[e], o);
    }
    if (lane == 0) {
        float mx = acc[0];
        int mi = 0;
#pragma unroll
        for (int e = 1; e < NEXP; e++) {
            if (acc[e] > mx) { mx = acc[e]; mi = e; }   // strict >: first-max like jnp.argmax
        }
        float den = 0.f;
#pragma unroll
        for (int e = 0; e < NEXP; e++) den += expf(acc[e] - mx);
        g_eidx[s] = mi;
        g_gval[s] = 1.0f / den;   // softmax value at argmax = exp(0)/den
    }
}

// ---------------------------------------------------------------------------
// Scan: exact in-order cumsum positions per expert; capacity drop; builds
// slot_token / slot_gate. One block, 256 threads, 32 tokens each.
// ---------------------------------------------------------------------------
__global__ __launch_bounds__(256)
void scan_kernel() {
    __shared__ int cnt[256][NEXP + 1];   // +1 pad: kill 8-way bank conflicts
    int tid = threadIdx.x;

    // init slot arrays
    for (int i = tid; i < NEXP * CAP; i += 256) {
        g_slot_token[i] = -1;
        g_slot_gate[i]  = 0.f;
    }

    int local[NEXP];
#pragma unroll
    for (int e = 0; e < NEXP; e++) local[e] = 0;

    int base = tid * 32;
    for (int t = 0; t < 32; t++) local[g_eidx[base + t]]++;
#pragma unroll
    for (int e = 0; e < NEXP; e++) cnt[tid][e] = local[e];
    __syncthreads();

    // Hillis-Steele inclusive scan over 256 threads (8-vector)
    for (int off = 1; off < 256; off <<= 1) {
        int add[NEXP];
        if (tid >= off) {
#pragma unroll
            for (int e = 0; e < NEXP; e++) add[e] = cnt[tid - off][e];
        }
        __syncthreads();
        if (tid >= off) {
#pragma unroll
            for (int e = 0; e < NEXP; e++) cnt[tid][e] += add[e];
        }
        __syncthreads();
    }

    int run[NEXP];
#pragma unroll
    for (int e = 0; e < NEXP; e++) run[e] = cnt[tid][e] - local[e];   // exclusive

    for (int t = 0; t < 32; t++) {
        int s = base + t;
        int e = g_eidx[s];
        int p = run[e]++;
        if (p < CAP) {
            g_slot_token[e * CAP + p] = s;
            g_slot_gate[e * CAP + p]  = g_gval[s];
        }
    }
}

// ---------------------------------------------------------------------------
// Zero output (d_out poisoned; dropped tokens must read exactly 0).
// ---------------------------------------------------------------------------
__global__ void zero_out_kernel(float4* __restrict__ out, int n4) {
    int i = blockIdx.x * blockDim.x + threadIdx.x;
    if (i < n4) out[i] = make_float4(0.f, 0.f, 0.f, 0.f);
}

// ---------------------------------------------------------------------------
// GEMM1: h[e,c,:] = gelu( gathered_x[e,c,:] @ W1[e] + b1[e] )
// A gathered from x via slot_token (empty slot -> zeros).
// 128x128 tile, BK=16, 256 threads, 8x8 per thread.
// ---------------------------------------------------------------------------
__global__ __launch_bounds__(256, 2)
void gemm1_kernel(const float* __restrict__ x,
                  const float* __restrict__ w1,
                  const float* __restrict__ b1) {
    __shared__ float As[16][132];
    __shared__ float Bs[16][132];

    const int e    = blockIdx.z;
    const int row0 = blockIdx.y * 128;
    const int col0 = blockIdx.x * 128;
    const int tid  = threadIdx.x;

    const float* B = w1 + (size_t)e * MDIM * HDIM;

    const int ar  = tid >> 2;          // 0..63
    const int ac4 = (tid & 3) * 4;
    const int tok0 = g_slot_token[e * CAP + row0 + ar];
    const int tok1 = g_slot_token[e * CAP + row0 + ar + 64];

    const int br  = tid >> 5;          // 0..7
    const int bc4 = (tid & 31) * 4;

    const int ty = tid >> 4, tx = tid & 15;

    float acc[8][8];
#pragma unroll
    for (int i = 0; i < 8; i++)
#pragma unroll
        for (int j = 0; j < 8; j++) acc[i][j] = 0.f;

    for (int kt = 0; kt < MDIM; kt += 16) {
        float4 a0 = make_float4(0.f, 0.f, 0.f, 0.f);
        float4 a1 = a0;
        if (tok0 >= 0) a0 = *reinterpret_cast<const float4*>(x + (size_t)tok0 * MDIM + kt + ac4);
        if (tok1 >= 0) a1 = *reinterpret_cast<const float4*>(x + (size_t)tok1 * MDIM + kt + ac4);
        As[ac4 + 0][ar] = a0.x; As[ac4 + 1][ar] = a0.y;
        As[ac4 + 2][ar] = a0.z; As[ac4 + 3][ar] = a0.w;
        As[ac4 + 0][ar + 64] = a1.x; As[ac4 + 1][ar + 64] = a1.y;
        As[ac4 + 2][ar + 64] = a1.z; As[ac4 + 3][ar + 64] = a1.w;

        float4 bv0 = *reinterpret_cast<const float4*>(B + (size_t)(kt + br)     * HDIM + col0 + bc4);
        float4 bv1 = *reinterpret_cast<const float4*>(B + (size_t)(kt + br + 8) * HDIM + col0 + bc4);
        *reinterpret_cast<float4*>(&Bs[br][bc4])     = bv0;
        *reinterpret_cast<float4*>(&Bs[br + 8][bc4]) = bv1;
        __syncthreads();

#pragma unroll
        for (int kk = 0; kk < 16; kk++) {
            float a[8], b[8];
            *reinterpret_cast<float4*>(a)     = *reinterpret_cast<float4*>(&As[kk][ty * 8]);
            *reinterpret_cast<float4*>(a + 4) = *reinterpret_cast<float4*>(&As[kk][ty * 8 + 4]);
            *reinterpret_cast<float4*>(b)     = *reinterpret_cast<float4*>(&Bs[kk][tx * 8]);
            *reinterpret_cast<float4*>(b + 4) = *reinterpret_cast<float4*>(&Bs[kk][tx * 8 + 4]);
#pragma unroll
            for (int i = 0; i < 8; i++)
#pragma unroll
                for (int j = 0; j < 8; j++) acc[i][j] += a[i] * b[j];
        }
        __syncthreads();
    }

    // epilogue: + b1, gelu, store to g_h
#pragma unroll
    for (int i = 0; i < 8; i++) {
        int row = row0 + ty * 8 + i;
        float* hrow = g_h + ((size_t)e * CAP + row) * HDIM;
#pragma unroll
        for (int j = 0; j < 8; j++) {
            int col = col0 + tx * 8 + j;
            float v = acc[i][j] + b1[e * HDIM + col];
            hrow[col] = gelu_exact(v);
        }
    }
}

// ---------------------------------------------------------------------------
// GEMM2: out[token,:] += gate * ( h[e,c,:] @ W2[e] + b2[e] )  (scatter-combine)
// ---------------------------------------------------------------------------
__global__ __launch_bounds__(256, 2)
void gemm2_kernel(const float* __restrict__ w2,
                  const float* __restrict__ b2,
                  float* __restrict__ out) {
    __shared__ float As[16][132];
    __shared__ float Bs[16][132];

    const int e    = blockIdx.z;
    const int row0 = blockIdx.y * 128;
    const int col0 = blockIdx.x * 128;
    const int tid  = threadIdx.x;

    const float* A = g_h + (size_t)e * CAP * HDIM;
    const float* B = w2  + (size_t)e * HDIM * MDIM;

    const int ar  = tid >> 2;
    const int ac4 = (tid & 3) * 4;
    const int br  = tid >> 5;
    const int bc4 = (tid & 31) * 4;
    const int ty = tid >> 4, tx = tid & 15;

    float acc[8][8];
#pragma unroll
    for (int i = 0; i < 8; i++)
#pragma unroll
        for (int j = 0; j < 8; j++) acc[i][j] = 0.f;

    for (int kt = 0; kt < HDIM; kt += 16) {
        float4 a0 = *reinterpret_cast<const float4*>(A + (size_t)(row0 + ar)      * HDIM + kt + ac4);
        float4 a1 = *reinterpret_cast<const float4*>(A + (size_t)(row0 + ar + 64) * HDIM + kt + ac4);
        As[ac4 + 0][ar] = a0.x; As[ac4 + 1][ar] = a0.y;
        As[ac4 + 2][ar] = a0.z; As[ac4 + 3][ar] = a0.w;
        As[ac4 + 0][ar + 64] = a1.x; As[ac4 + 1][ar + 64] = a1.y;
        As[ac4 + 2][ar + 64] = a1.z; As[ac4 + 3][ar + 64] = a1.w;

        float4 bv0 = *reinterpret_cast<const float4*>(B + (size_t)(kt + br)     * MDIM + col0 + bc4);
        float4 bv1 = *reinterpret_cast<const float4*>(B + (size_t)(kt + br + 8) * MDIM + col0 + bc4);
        *reinterpret_cast<float4*>(&Bs[br][bc4])     = bv0;
        *reinterpret_cast<float4*>(&Bs[br + 8][bc4]) = bv1;
        __syncthreads();

#pragma unroll
        for (int kk = 0; kk < 16; kk++) {
            float a[8], b[8];
            *reinterpret_cast<float4*>(a)     = *reinterpret_cast<float4*>(&As[kk][ty * 8]);
            *reinterpret_cast<float4*>(a + 4) = *reinterpret_cast<float4*>(&As[kk][ty * 8 + 4]);
            *reinterpret_cast<float4*>(b)     = *reinterpret_cast<float4*>(&Bs[kk][tx * 8]);
            *reinterpret_cast<float4*>(b + 4) = *reinterpret_cast<float4*>(&Bs[kk][tx * 8 + 4]);
#pragma unroll
            for (int i = 0; i < 8; i++)
#pragma unroll
                for (int j = 0; j < 8; j++) acc[i][j] += a[i] * b[j];
        }
        __syncthreads();
    }

    // epilogue: scatter gate * (acc + b2) to output rows of kept tokens
#pragma unroll
    for (int i = 0; i < 8; i++) {
        int row = row0 + ty * 8 + i;
        int tok = g_slot_token[e * CAP + row];
        if (tok < 0) continue;
        float g = g_slot_gate[e * CAP + row];
        float* orow = out + (size_t)tok * MDIM;
#pragma unroll
        for (int j = 0; j < 8; j++) {
            int col = col0 + tx * 8 + j;
            orow[col] = g * (acc[i][j] + b2[e * MDIM + col]);
        }
    }
}

// ---------------------------------------------------------------------------
extern "C" void kernel_launch(void* const* d_in, const int* in_sizes, int n_in,
                              void* d_out, int out_size) {
    const float* x   = (const float*)d_in[0];   // [S, M]
    const float* wg  = (const float*)d_in[1];   // [M, E]
    const float* w1  = (const float*)d_in[2];   // [E, M, H]
    const float* b1  = (const float*)d_in[3];   // [E, H]
    const float* w2  = (const float*)d_in[4];   // [E, H, M]
    const float* b2  = (const float*)d_in[5];   // [E, M]
    float* out = (float*)d_out;                 // [S, M]

    gate_kernel<<<S_TOK / 8, 256>>>(x, wg);
    scan_kernel<<<1, 256>>>();

    int n4 = (S_TOK * MDIM) / 4;
    zero_out_kernel<<<(n4 + 255) / 256, 256>>>((float4*)out, n4);

    dim3 g1(HDIM / 128, CAP / 128, NEXP);   // 32 x 8 x 8
    gemm1_kernel<<<g1, 256>>>(x, w1, b1);

    dim3 g2(MDIM / 128, CAP / 128, NEXP);   // 8 x 8 x 8
    gemm2_kernel<<<g2, 256>>>(w2, b2, out);
}

// round 8
// speedup vs baseline: 1.1372x; 1.1372x over previous
#include <cuda_runtime.h>
#include <mma.h>
#include <math.h>
#include <stdint.h>

using namespace nvcuda;

#define S_TOK 8192
#define MDIM  1024
#define HDIM  4096
#define NEXP  8
#define CAP   1024   // S/E, capacity 1.0, k=1

// ---------------- scratch (__device__ globals; no runtime alloc allowed) ----
// Referenced ONLY from device code (host-side symbol address is a stub — UB).
__device__ __align__(256) int   g_eidx[S_TOK];
__device__ __align__(256) float g_gval[S_TOK];
__device__ __align__(256) int   g_slot_token[NEXP * CAP];
__device__ __align__(256) float g_slot_gate[NEXP * CAP];
__device__ __align__(256) float g_h[(size_t)NEXP * CAP * HDIM];   // 128 MB hidden
__device__ __align__(256) float g_y[(size_t)NEXP * CAP * MDIM];   //  32 MB expert outputs

// ------------------------------- helpers -----------------------------------
__device__ __forceinline__ float gelu_exact(float v) {
    return 0.5f * v * (1.0f + erff(v * 0.70710678118654752440f));
}

// ---------------------------------------------------------------------------
// Gate: logits = x @ wg; softmax; argmax.   (round-1 proven, ran in round 6)
// ---------------------------------------------------------------------------
__global__ __launch_bounds__(256)
void gate_kernel(const float* __restrict__ x, const float* __restrict__ wg) {
    __shared__ float swg[MDIM * NEXP];
    for (int i = threadIdx.x; i < MDIM * NEXP; i += blockDim.x) swg[i] = wg[i];
    __syncthreads();

    int warp = threadIdx.x >> 5;
    int lane = threadIdx.x & 31;
    int s = blockIdx.x * 8 + warp;
    if (s >= S_TOK) return;

    const float* xr = x + (size_t)s * MDIM;
    float acc[NEXP];
#pragma unroll
    for (int e = 0; e < NEXP; e++) acc[e] = 0.f;

    for (int k = lane; k < MDIM; k += 32) {
        float xv = xr[k];
#pragma unroll
        for (int e = 0; e < NEXP; e++) acc[e] += xv * swg[k * NEXP + e];
    }
#pragma unroll
    for (int e = 0; e < NEXP; e++) {
#pragma unroll
        for (int o = 16; o > 0; o >>= 1) acc[e] += __shfl_xor_sync(0xFFFFFFFFu, acc[e], o);
    }
    if (lane == 0) {
        float mx = acc[0];
        int mi = 0;
#pragma unroll
        for (int e = 1; e < NEXP; e++) {
            if (acc[e] > mx) { mx = acc[e]; mi = e; }
        }
        float den = 0.f;
#pragma unroll
        for (int e = 0; e < NEXP; e++) den += expf(acc[e] - mx);
        g_eidx[s] = mi;
        g_gval[s] = 1.0f / den;
    }
}

// ---------------------------------------------------------------------------
// Scan: exact in-order per-expert positions + capacity drop. (proven)
// ---------------------------------------------------------------------------
__global__ __launch_bounds__(256)
void scan_kernel() {
    __shared__ int cnt[256][NEXP + 1];
    int tid = threadIdx.x;

    for (int i = tid; i < NEXP * CAP; i += 256) {
        g_slot_token[i] = -1;
        g_slot_gate[i]  = 0.f;
    }

    int local[NEXP];
#pragma unroll
    for (int e = 0; e < NEXP; e++) local[e] = 0;

    int base = tid * 32;
    for (int t = 0; t < 32; t++) local[g_eidx[base + t]]++;
#pragma unroll
    for (int e = 0; e < NEXP; e++) cnt[tid][e] = local[e];
    __syncthreads();

    for (int off = 1; off < 256; off <<= 1) {
        int add[NEXP];
        if (tid >= off) {
#pragma unroll
            for (int e = 0; e < NEXP; e++) add[e] = cnt[tid - off][e];
        }
        __syncthreads();
        if (tid >= off) {
#pragma unroll
            for (int e = 0; e < NEXP; e++) cnt[tid][e] += add[e];
        }
        __syncthreads();
    }

    int run[NEXP];
#pragma unroll
    for (int e = 0; e < NEXP; e++) run[e] = cnt[tid][e] - local[e];

    for (int t = 0; t < 32; t++) {
        int s = base + t;
        int e = g_eidx[s];
        int p = run[e]++;
        if (p < CAP) {
            g_slot_token[e * CAP + p] = s;
            g_slot_gate[e * CAP + p]  = g_gval[s];
        }
    }
}

// ---------------------------------------------------------------------------
__global__ void zero_out_kernel(float4* __restrict__ out, int n4) {
    int i = blockIdx.x * blockDim.x + threadIdx.x;
    if (i < n4) out[i] = make_float4(0.f, 0.f, 0.f, 0.f);
}

// ---------------------------------------------------------------------------
// WMMA tf32 GEMM (official API; static smem; plain LDG/STS; register
// double-buffer prefetch). Structure identical to round 6, which executed.
// CTA tile 128x128, K-tile 32, 8 warps, warp tile 32x64 (2x4 16x16 frags).
// GATHER=true : A rows gathered from x (arg) via slot_token; C -> g_h (internal)
// GATHER=false: A = g_h (internal); C -> g_y (internal)
// ---------------------------------------------------------------------------
#define A_LD 40     // 160 B row stride (mult of 32 B for wmma)
#define B_LD 136    // 544 B row stride (mult of 32 B)

template <int KDIM, int NTOT, bool GATHER>
__global__ __launch_bounds__(256)
void wmma_gemm_kernel(const float* __restrict__ Xin,   // x (harness ptr); used iff GATHER
                      const float* __restrict__ Bw) {  // weights [E][KDIM][NTOT] (harness ptr)
    __shared__ __align__(32) float As[128][A_LD];
    __shared__ __align__(32) float Bs[32][B_LD];

    const int tid  = threadIdx.x;
    const int e    = blockIdx.y >> 3;
    const int row0 = (blockIdx.y & 7) * 128;
    const int n0   = blockIdx.x * 128;

    // A loader: 2 threads per row, 16 floats (4x float4) each
    const int ar = tid >> 1;                 // 0..127
    const int ac = (tid & 1) * 16;           // 0 or 16
    const float* a_row;
    if constexpr (GATHER) {
        int tok = g_slot_token[e * CAP + row0 + ar];
        a_row = (tok >= 0) ? (Xin + (size_t)tok * KDIM) : nullptr;
    } else {
        a_row = g_h + (size_t)(e * CAP + row0 + ar) * KDIM;   // device-side ref
    }

    // B loader: 8 threads per row, 16 floats each
    const int br = tid >> 3;                 // 0..31
    const int bc = (tid & 7) * 16;           // 0..112
    const float* b_row = Bw + (size_t)e * KDIM * NTOT + n0 + bc;

    const int wid = tid >> 5;
    const int wm  = (wid & 3) * 32;
    const int wn  = (wid >> 2) * 64;

    wmma::fragment<wmma::accumulator, 16, 16, 8, float> acc[2][4];
#pragma unroll
    for (int mm = 0; mm < 2; mm++)
#pragma unroll
        for (int nn = 0; nn < 4; nn++) wmma::fill_fragment(acc[mm][nn], 0.f);

    float4 aR[4], bR[4];

    auto fetch = [&](int kt) {
        if (a_row) {
#pragma unroll
            for (int i = 0; i < 4; i++)
                aR[i] = *(const float4*)(a_row + kt + ac + i * 4);
        } else {
#pragma unroll
            for (int i = 0; i < 4; i++) aR[i] = make_float4(0.f, 0.f, 0.f, 0.f);
        }
        const float* bp = b_row + (size_t)(kt + br) * NTOT;
#pragma unroll
        for (int i = 0; i < 4; i++)
            bR[i] = *(const float4*)(bp + i * 4);
    };
    auto commit = [&]() {
#pragma unroll
        for (int i = 0; i < 4; i++) {
            As[ar][ac + i * 4 + 0] = wmma::__float_to_tf32(aR[i].x);
            As[ar][ac + i * 4 + 1] = wmma::__float_to_tf32(aR[i].y);
            As[ar][ac + i * 4 + 2] = wmma::__float_to_tf32(aR[i].z);
            As[ar][ac + i * 4 + 3] = wmma::__float_to_tf32(aR[i].w);
        }
#pragma unroll
        for (int i = 0; i < 4; i++) {
            Bs[br][bc + i * 4 + 0] = wmma::__float_to_tf32(bR[i].x);
            Bs[br][bc + i * 4 + 1] = wmma::__float_to_tf32(bR[i].y);
            Bs[br][bc + i * 4 + 2] = wmma::__float_to_tf32(bR[i].z);
            Bs[br][bc + i * 4 + 3] = wmma::__float_to_tf32(bR[i].w);
        }
    };

    fetch(0);
    for (int kt = 0; kt < KDIM; kt += 32) {
        commit();
        __syncthreads();
        if (kt + 32 < KDIM) fetch(kt + 32);   // prefetch next tile under compute

#pragma unroll
        for (int k8 = 0; k8 < 4; k8++) {
            wmma::fragment<wmma::matrix_a, 16, 16, 8, wmma::precision::tf32, wmma::row_major> af[2];
            wmma::fragment<wmma::matrix_b, 16, 16, 8, wmma::precision::tf32, wmma::row_major> bf[4];
#pragma unroll
            for (int mm = 0; mm < 2; mm++)
                wmma::load_matrix_sync(af[mm], &As[wm + mm * 16][k8 * 8], A_LD);
#pragma unroll
            for (int nn = 0; nn < 4; nn++)
                wmma::load_matrix_sync(bf[nn], &Bs[k8 * 8][wn + nn * 16], B_LD);
#pragma unroll
            for (int mm = 0; mm < 2; mm++)
#pragma unroll
                for (int nn = 0; nn < 4; nn++)
                    wmma::mma_sync(acc[mm][nn], af[mm], bf[nn], acc[mm][nn]);
        }
        __syncthreads();
    }

    // ---- store raw C to the internal scratch for this GEMM ----
    float* Cbase = GATHER ? g_h : g_y;       // device-side reference
#pragma unroll
    for (int mm = 0; mm < 2; mm++) {
        float* crow = Cbase + (size_t)(e * CAP + row0 + wm + mm * 16) * NTOT + n0 + wn;
#pragma unroll
        for (int nn = 0; nn < 4; nn++)
            wmma::store_matrix_sync(crow + nn * 16, acc[mm][nn], NTOT, wmma::mem_row_major);
    }
}

// ---------------------------------------------------------------------------
// Elementwise: g_h = gelu(g_h + b1[e])
// ---------------------------------------------------------------------------
__global__ __launch_bounds__(256)
void gelu_bias_kernel(const float* __restrict__ b1) {
    int row = blockIdx.x;                 // 0..8191  (= e*CAP + c)
    int e   = row >> 10;
    float* hp = g_h + (size_t)row * HDIM;
    const float* bp = b1 + e * HDIM;
    for (int j = threadIdx.x; j < HDIM / 4; j += 256) {
        float4 v = ((const float4*)hp)[j];
        float4 b = ((const float4*)bp)[j];
        v.x = gelu_exact(v.x + b.x);
        v.y = gelu_exact(v.y + b.y);
        v.z = gelu_exact(v.z + b.z);
        v.w = gelu_exact(v.w + b.w);
        ((float4*)hp)[j] = v;
    }
}

// ---------------------------------------------------------------------------
// Combine: out[tok] = gate * (g_y[slot] + b2[e])   (dropped tokens stay 0)
// ---------------------------------------------------------------------------
__global__ __launch_bounds__(256)
void combine_kernel(const float* __restrict__ b2, float* __restrict__ out) {
    int slot = blockIdx.x;                // 0..8191
    int tok  = g_slot_token[slot];
    if (tok < 0) return;
    int e = slot >> 10;
    float gv = g_slot_gate[slot];
    const float* yp = g_y + (size_t)slot * MDIM;
    const float* bp = b2 + e * MDIM;
    float* op = out + (size_t)tok * MDIM;
    for (int j = threadIdx.x; j < MDIM / 4; j += 256) {
        float4 v = ((const float4*)yp)[j];
        float4 b = ((const float4*)bp)[j];
        v.x = gv * (v.x + b.x);
        v.y = gv * (v.y + b.y);
        v.z = gv * (v.z + b.z);
        v.w = gv * (v.w + b.w);
        ((float4*)op)[j] = v;
    }
}

// ---------------------------------------------------------------------------
extern "C" void kernel_launch(void* const* d_in, const int* in_sizes, int n_in,
                              void* d_out, int out_size) {
    const float* x   = (const float*)d_in[0];   // [S, M]
    const float* wg  = (const float*)d_in[1];   // [M, E]
    const float* w1  = (const float*)d_in[2];   // [E, M, H]
    const float* b1  = (const float*)d_in[3];   // [E, H]
    const float* w2  = (const float*)d_in[4];   // [E, H, M]
    const float* b2  = (const float*)d_in[5];   // [E, M]
    float* out = (float*)d_out;                 // [S, M]

    gate_kernel<<<S_TOK / 8, 256>>>(x, wg);
    scan_kernel<<<1, 256>>>();

    int n4 = (S_TOK * MDIM) / 4;
    zero_out_kernel<<<(n4 + 255) / 256, 256>>>((float4*)out, n4);

    // GEMM1: g_h(raw) = gathered_x @ W1   (A from x arg; C -> g_h internal)
    wmma_gemm_kernel<MDIM, HDIM, true><<<dim3(HDIM / 128, NEXP * 8), 256>>>(x, w1);
    // g_h = gelu(g_h + b1)
    gelu_bias_kernel<<<NEXP * CAP, 256>>>(b1);
    // GEMM2: g_y(raw) = g_h @ W2          (A internal; C -> g_y internal)
    wmma_gemm_kernel<HDIM, MDIM, false><<<dim3(MDIM / 128, NEXP * 8), 256>>>(x, w2);
    // out[tok] = gate * (g_y + b2)
    combine_kernel<<<NEXP * CAP, 256>>>(b2, out);
}

// round 9
// speedup vs baseline: 1.4099x; 1.2398x over previous
#include <cuda_runtime.h>
#include <mma.h>
#include <math.h>
#include <stdint.h>

using namespace nvcuda;

#define S_TOK 8192
#define MDIM  1024
#define HDIM  4096
#define NEXP  8
#define CAP   1024   // S/E, capacity 1.0, k=1

// ---------------- scratch (__device__ globals; no runtime alloc allowed) ----
// Referenced ONLY from device code (host-side symbol address is a stub — UB).
__device__ __align__(256) int   g_eidx[S_TOK];
__device__ __align__(256) float g_gval[S_TOK];
__device__ __align__(256) int   g_slot_token[NEXP * CAP];
__device__ __align__(256) float g_slot_gate[NEXP * CAP];
__device__ __align__(256) float g_h[(size_t)NEXP * CAP * HDIM];   // 128 MB hidden
__device__ __align__(256) float g_y[(size_t)NEXP * CAP * MDIM];   //  32 MB expert outputs

// ------------------------------- helpers -----------------------------------
__device__ __forceinline__ float gelu_exact(float v) {
    return 0.5f * v * (1.0f + erff(v * 0.70710678118654752440f));
}

// ---------------------------------------------------------------------------
// Gate: logits = x @ wg; softmax; argmax.   (proven)
// ---------------------------------------------------------------------------
__global__ __launch_bounds__(256)
void gate_kernel(const float* __restrict__ x, const float* __restrict__ wg) {
    __shared__ float swg[MDIM * NEXP];
    for (int i = threadIdx.x; i < MDIM * NEXP; i += blockDim.x) swg[i] = wg[i];
    __syncthreads();

    int warp = threadIdx.x >> 5;
    int lane = threadIdx.x & 31;
    int s = blockIdx.x * 8 + warp;
    if (s >= S_TOK) return;

    const float* xr = x + (size_t)s * MDIM;
    float acc[NEXP];
#pragma unroll
    for (int e = 0; e < NEXP; e++) acc[e] = 0.f;

    for (int k = lane; k < MDIM; k += 32) {
        float xv = xr[k];
#pragma unroll
        for (int e = 0; e < NEXP; e++) acc[e] += xv * swg[k * NEXP + e];
    }
#pragma unroll
    for (int e = 0; e < NEXP; e++) {
#pragma unroll
        for (int o = 16; o > 0; o >>= 1) acc[e] += __shfl_xor_sync(0xFFFFFFFFu, acc[e], o);
    }
    if (lane == 0) {
        float mx = acc[0];
        int mi = 0;
#pragma unroll
        for (int e = 1; e < NEXP; e++) {
            if (acc[e] > mx) { mx = acc[e]; mi = e; }
        }
        float den = 0.f;
#pragma unroll
        for (int e = 0; e < NEXP; e++) den += expf(acc[e] - mx);
        g_eidx[s] = mi;
        g_gval[s] = 1.0f / den;
    }
}

// ---------------------------------------------------------------------------
// Scan: exact in-order per-expert positions + capacity drop. (proven)
// ---------------------------------------------------------------------------
__global__ __launch_bounds__(256)
void scan_kernel() {
    __shared__ int cnt[256][NEXP + 1];
    int tid = threadIdx.x;

    for (int i = tid; i < NEXP * CAP; i += 256) {
        g_slot_token[i] = -1;
        g_slot_gate[i]  = 0.f;
    }

    int local[NEXP];
#pragma unroll
    for (int e = 0; e < NEXP; e++) local[e] = 0;

    int base = tid * 32;
    for (int t = 0; t < 32; t++) local[g_eidx[base + t]]++;
#pragma unroll
    for (int e = 0; e < NEXP; e++) cnt[tid][e] = local[e];
    __syncthreads();

    for (int off = 1; off < 256; off <<= 1) {
        int add[NEXP];
        if (tid >= off) {
#pragma unroll
            for (int e = 0; e < NEXP; e++) add[e] = cnt[tid - off][e];
        }
        __syncthreads();
        if (tid >= off) {
#pragma unroll
            for (int e = 0; e < NEXP; e++) cnt[tid][e] += add[e];
        }
        __syncthreads();
    }

    int run[NEXP];
#pragma unroll
    for (int e = 0; e < NEXP; e++) run[e] = cnt[tid][e] - local[e];

    for (int t = 0; t < 32; t++) {
        int s = base + t;
        int e = g_eidx[s];
        int p = run[e]++;
        if (p < CAP) {
            g_slot_token[e * CAP + p] = s;
            g_slot_gate[e * CAP + p]  = g_gval[s];
        }
    }
}

// ---------------------------------------------------------------------------
__global__ void zero_out_kernel(float4* __restrict__ out, int n4) {
    int i = blockIdx.x * blockDim.x + threadIdx.x;
    if (i < n4) out[i] = make_float4(0.f, 0.f, 0.f, 0.f);
}

// ---------------------------------------------------------------------------
// WMMA tf32 GEMM. Identical structure to the round-8 passing kernel, minus
// the register prefetch (saves ~32 regs) and with __launch_bounds__(256, 2)
// to force 2 CTAs/SM (round 8: 184 regs -> 1 CTA/SM -> issue 19%).
// CTA tile 128x128, K-tile 32, 8 warps, warp tile 32x64 (2x4 16x16 frags).
// GATHER=true : A rows gathered from x (arg) via slot_token; C -> g_h (internal)
// GATHER=false: A = g_h (internal); C -> g_y (internal)
// ---------------------------------------------------------------------------
#define A_LD 40     // 160 B row stride (mult of 32 B for wmma)
#define B_LD 136    // 544 B row stride (mult of 32 B)

template <int KDIM, int NTOT, bool GATHER>
__global__ __launch_bounds__(256, 2)
void wmma_gemm_kernel(const float* __restrict__ Xin,   // x (harness ptr); used iff GATHER
                      const float* __restrict__ Bw) {  // weights [E][KDIM][NTOT] (harness ptr)
    __shared__ __align__(32) float As[128][A_LD];
    __shared__ __align__(32) float Bs[32][B_LD];

    const int tid  = threadIdx.x;
    const int e    = blockIdx.y >> 3;
    const int row0 = (blockIdx.y & 7) * 128;
    const int n0   = blockIdx.x * 128;

    // A loader: 2 threads per row, 16 floats (4x float4) each
    const int ar = tid >> 1;                 // 0..127
    const int ac = (tid & 1) * 16;           // 0 or 16
    const float* a_row;
    if constexpr (GATHER) {
        int tok = g_slot_token[e * CAP + row0 + ar];
        a_row = (tok >= 0) ? (Xin + (size_t)tok * KDIM) : nullptr;
    } else {
        a_row = g_h + (size_t)(e * CAP + row0 + ar) * KDIM;   // device-side ref
    }

    // B loader: 8 threads per row, 16 floats each
    const int br = tid >> 3;                 // 0..31
    const int bc = (tid & 7) * 16;           // 0..112
    const float* b_row = Bw + (size_t)e * KDIM * NTOT + n0 + bc;

    const int wid = tid >> 5;
    const int wm  = (wid & 3) * 32;
    const int wn  = (wid >> 2) * 64;

    wmma::fragment<wmma::accumulator, 16, 16, 8, float> acc[2][4];
#pragma unroll
    for (int mm = 0; mm < 2; mm++)
#pragma unroll
        for (int nn = 0; nn < 4; nn++) wmma::fill_fragment(acc[mm][nn], 0.f);

    for (int kt = 0; kt < KDIM; kt += 32) {
        // ---- load tile straight to smem (latency hidden by co-resident CTA) ----
        if (a_row) {
#pragma unroll
            for (int i = 0; i < 4; i++) {
                float4 v = *(const float4*)(a_row + kt + ac + i * 4);
                As[ar][ac + i * 4 + 0] = wmma::__float_to_tf32(v.x);
                As[ar][ac + i * 4 + 1] = wmma::__float_to_tf32(v.y);
                As[ar][ac + i * 4 + 2] = wmma::__float_to_tf32(v.z);
                As[ar][ac + i * 4 + 3] = wmma::__float_to_tf32(v.w);
            }
        } else {
#pragma unroll
            for (int i = 0; i < 4; i++) {
                As[ar][ac + i * 4 + 0] = 0.f;
                As[ar][ac + i * 4 + 1] = 0.f;
                As[ar][ac + i * 4 + 2] = 0.f;
                As[ar][ac + i * 4 + 3] = 0.f;
            }
        }
        {
            const float* bp = b_row + (size_t)(kt + br) * NTOT;
#pragma unroll
            for (int i = 0; i < 4; i++) {
                float4 v = *(const float4*)(bp + i * 4);
                Bs[br][bc + i * 4 + 0] = wmma::__float_to_tf32(v.x);
                Bs[br][bc + i * 4 + 1] = wmma::__float_to_tf32(v.y);
                Bs[br][bc + i * 4 + 2] = wmma::__float_to_tf32(v.z);
                Bs[br][bc + i * 4 + 3] = wmma::__float_to_tf32(v.w);
            }
        }
        __syncthreads();

#pragma unroll
        for (int k8 = 0; k8 < 4; k8++) {
            wmma::fragment<wmma::matrix_a, 16, 16, 8, wmma::precision::tf32, wmma::row_major> af[2];
            wmma::fragment<wmma::matrix_b, 16, 16, 8, wmma::precision::tf32, wmma::row_major> bf[4];
#pragma unroll
            for (int mm = 0; mm < 2; mm++)
                wmma::load_matrix_sync(af[mm], &As[wm + mm * 16][k8 * 8], A_LD);
#pragma unroll
            for (int nn = 0; nn < 4; nn++)
                wmma::load_matrix_sync(bf[nn], &Bs[k8 * 8][wn + nn * 16], B_LD);
#pragma unroll
            for (int mm = 0; mm < 2; mm++)
#pragma unroll
                for (int nn = 0; nn < 4; nn++)
                    wmma::mma_sync(acc[mm][nn], af[mm], bf[nn], acc[mm][nn]);
        }
        __syncthreads();
    }

    // ---- store raw C to the internal scratch for this GEMM ----
    float* Cbase = GATHER ? g_h : g_y;       // device-side reference
#pragma unroll
    for (int mm = 0; mm < 2; mm++) {
        float* crow = Cbase + (size_t)(e * CAP + row0 + wm + mm * 16) * NTOT + n0 + wn;
#pragma unroll
        for (int nn = 0; nn < 4; nn++)
            wmma::store_matrix_sync(crow + nn * 16, acc[mm][nn], NTOT, wmma::mem_row_major);
    }
}

// ---------------------------------------------------------------------------
// Elementwise: g_h = gelu(g_h + b1[e])
// ---------------------------------------------------------------------------
__global__ __launch_bounds__(256)
void gelu_bias_kernel(const float* __restrict__ b1) {
    int row = blockIdx.x;                 // 0..8191  (= e*CAP + c)
    int e   = row >> 10;
    float* hp = g_h + (size_t)row * HDIM;
    const float* bp = b1 + e * HDIM;
    for (int j = threadIdx.x; j < HDIM / 4; j += 256) {
        float4 v = ((const float4*)hp)[j];
        float4 b = ((const float4*)bp)[j];
        v.x = gelu_exact(v.x + b.x);
        v.y = gelu_exact(v.y + b.y);
        v.z = gelu_exact(v.z + b.z);
        v.w = gelu_exact(v.w + b.w);
        ((float4*)hp)[j] = v;
    }
}

// ---------------------------------------------------------------------------
// Combine: out[tok] = gate * (g_y[slot] + b2[e])   (dropped tokens stay 0)
// ---------------------------------------------------------------------------
__global__ __launch_bounds__(256)
void combine_kernel(const float* __restrict__ b2, float* __restrict__ out) {
    int slot = blockIdx.x;                // 0..8191
    int tok  = g_slot_token[slot];
    if (tok < 0) return;
    int e = slot >> 10;
    float gv = g_slot_gate[slot];
    const float* yp = g_y + (size_t)slot * MDIM;
    const float* bp = b2 + e * MDIM;
    float* op = out + (size_t)tok * MDIM;
    for (int j = threadIdx.x; j < MDIM / 4; j += 256) {
        float4 v = ((const float4*)yp)[j];
        float4 b = ((const float4*)bp)[j];
        v.x = gv * (v.x + b.x);
        v.y = gv * (v.y + b.y);
        v.z = gv * (v.z + b.z);
        v.w = gv * (v.w + b.w);
        ((float4*)op)[j] = v;
    }
}

// ---------------------------------------------------------------------------
extern "C" void kernel_launch(void* const* d_in, const int* in_sizes, int n_in,
                              void* d_out, int out_size) {
    const float* x   = (const float*)d_in[0];   // [S, M]
    const float* wg  = (const float*)d_in[1];   // [M, E]
    const float* w1  = (const float*)d_in[2];   // [E, M, H]
    const float* b1  = (const float*)d_in[3];   // [E, H]
    const float* w2  = (const float*)d_in[4];   // [E, H, M]
    const float* b2  = (const float*)d_in[5];   // [E, M]
    float* out = (float*)d_out;                 // [S, M]

    gate_kernel<<<S_TOK / 8, 256>>>(x, wg);
    scan_kernel<<<1, 256>>>();

    int n4 = (S_TOK * MDIM) / 4;
    zero_out_kernel<<<(n4 + 255) / 256, 256>>>((float4*)out, n4);

    // GEMM1: g_h(raw) = gathered_x @ W1   (A from x arg; C -> g_h internal)
    wmma_gemm_kernel<MDIM, HDIM, true><<<dim3(HDIM / 128, NEXP * 8), 256>>>(x, w1);
    // g_h = gelu(g_h + b1)
    gelu_bias_kernel<<<NEXP * CAP, 256>>>(b1);
    // GEMM2: g_y(raw) = g_h @ W2          (A internal; C -> g_y internal)
    wmma_gemm_kernel<HDIM, MDIM, false><<<dim3(MDIM / 128, NEXP * 8), 256>>>(x, w2);
    // out[tok] = gate * (g_y + b2)
    combine_kernel<<<NEXP * CAP, 256>>>(b2, out);
}